// round 7
// baseline (speedup 1.0000x reference)
#include <cuda_runtime.h>
#include <cuda_bf16.h>
#include <cstdint>

#define N_ 128
#define C_ 81
#define A_ 8732
#define A4_ 2183          // A_/4 exactly
#define NB_ 2048          // histogram bins (top 11 bits of con)
#define FXS 4194304.0f    // 2^22 fixed-point scale

// Scratch (device globals — no allocations allowed)
__device__ unsigned            g_con[N_ * A_];     // focal bits (dl==0 rows), positives = 0u
__device__ unsigned            g_hist[N_ * NB_];   // per-row bucket counts   (memset each launch)
__device__ unsigned long long  g_bsumfx[N_ * NB_]; // per-row bucket fixed-pt sums (memset each launch)
__device__ float               g_partcon[N_ * 16];
__device__ int                 g_partpos[N_ * 16];
__device__ float               g_row[N_];
__device__ unsigned            g_count;            // self-resetting

// ---------------------------------------------------------------------------
// Kernel A: focal loss per anchor; also builds per-row bucket hist + sums
// via deterministic integer atomics (hidden under the memory stalls).
// grid = (9, N), block = 256. Whole block exits when domain_label != 0.
// ---------------------------------------------------------------------------
__global__ __launch_bounds__(256, 8) void kA_focal(const float* __restrict__ plabel,
                                                   const int*   __restrict__ glabel,
                                                   const int*   __restrict__ domain_label)
{
    const int n = blockIdx.y;
    if (domain_label[n] != 0) return;

    int idx = blockIdx.x * 256 + threadIdx.x;
    bool valid = (idx < A4_);
    int ii = valid ? idx : (A4_ - 1);

    const float4* P = (const float4*)(plabel + (size_t)n * C_ * A_) + ii;
    int4 g = ((const int4*)(glabel + (size_t)n * A_))[ii];

    float4 s  = make_float4(0.f, 0.f, 0.f, 0.f);
    float4 xg = make_float4(0.f, 0.f, 0.f, 0.f);
#pragma unroll 3
    for (int c = 0; c < C_; c++) {
        float4 x = __ldcs(P);
        P += A4_;
        if (c == g.x) xg.x = x.x;
        if (c == g.y) xg.y = x.y;
        if (c == g.z) xg.z = x.z;
        if (c == g.w) xg.w = x.w;
        s.x += __expf(x.x); s.y += __expf(x.y);
        s.z += __expf(x.z); s.w += __expf(x.w);
    }

    float lp0 = xg.x - __logf(s.x), lp1 = xg.y - __logf(s.y);
    float lp2 = xg.z - __logf(s.z), lp3 = xg.w - __logf(s.w);
    float o0 = 1.f - __expf(lp0), o1 = 1.f - __expf(lp1);
    float o2 = 1.f - __expf(lp2), o3 = 1.f - __expf(lp3);
    float c0 = -0.25f * o0 * o0 * lp0;
    float c1 = -0.25f * o1 * o1 * lp1;
    float c2 = -0.25f * o2 * o2 * lp2;
    float c3 = -0.25f * o3 * o3 * lp3;

    bool m0 = g.x > 0, m1 = g.y > 0, m2 = g.z > 0, m3 = g.w > 0;

    uint4 cw;
    cw.x = m0 ? 0u : __float_as_uint(c0);
    cw.y = m1 ? 0u : __float_as_uint(c1);
    cw.z = m2 ? 0u : __float_as_uint(c2);
    cw.w = m3 ? 0u : __float_as_uint(c3);
    ((uint4*)g_con)[(size_t)n * A4_ + ii] = cw;

    // bucket hist + fixed-point bucket sums (negatives only, skip exact zeros)
    if (valid) {
        unsigned* H = g_hist + (size_t)n * NB_;
        unsigned long long* F = g_bsumfx + (size_t)n * NB_;
        if (cw.x) { unsigned b = cw.x >> 21; atomicAdd(&H[b], 1u); atomicAdd(&F[b], (unsigned long long)__float2ull_rn(c0 * FXS)); }
        if (cw.y) { unsigned b = cw.y >> 21; atomicAdd(&H[b], 1u); atomicAdd(&F[b], (unsigned long long)__float2ull_rn(c1 * FXS)); }
        if (cw.z) { unsigned b = cw.z >> 21; atomicAdd(&H[b], 1u); atomicAdd(&F[b], (unsigned long long)__float2ull_rn(c2 * FXS)); }
        if (cw.w) { unsigned b = cw.w >> 21; atomicAdd(&H[b], 1u); atomicAdd(&F[b], (unsigned long long)__float2ull_rn(c3 * FXS)); }
    }

    float contrib = 0.f;
    int pc = 0;
    if (valid) {
        if (m0) { contrib += c0; pc++; }
        if (m1) { contrib += c1; pc++; }
        if (m2) { contrib += c2; pc++; }
        if (m3) { contrib += c3; pc++; }
    }
    for (int o = 16; o > 0; o >>= 1) {
        contrib += __shfl_down_sync(0xffffffffu, contrib, o);
        pc      += __shfl_down_sync(0xffffffffu, pc, o);
    }
    __shared__ float sw[8];
    __shared__ int   swp[8];
    int wid = threadIdx.x >> 5, lane = threadIdx.x & 31;
    if (lane == 0) { sw[wid] = contrib; swp[wid] = pc; }
    __syncthreads();
    if (threadIdx.x == 0) {
        float t = 0.f; int tp = 0;
#pragma unroll
        for (int j = 0; j < 8; j++) { t += sw[j]; tp += swp[j]; }
        g_partcon[n * 16 + blockIdx.x] = t;
        g_partpos[n * 16 + blockIdx.x] = tp;
    }
}

// ---------------------------------------------------------------------------
// Kernel T: per-row tail using precomputed bucket hist/sums.
// One suffix scan of 2048 bins -> boundary bucket; ONE scan of the con row
// collects boundary elements; tiny exact radix select among them.
// grid = N_, block = 1024. Last-arriving CTA computes the mean.
// ---------------------------------------------------------------------------
__global__ __launch_bounds__(1024) void kT_tail(const float* __restrict__ ploc,
                                                const float* __restrict__ gloc,
                                                const int*   __restrict__ glabel,
                                                const int*   __restrict__ domain_label,
                                                const float* __restrict__ dboxes,
                                                float* __restrict__ out)
{
    __shared__ __align__(16) unsigned s_list[8736];   // boundary-bucket values
    __shared__ unsigned           s_hist[256];
    __shared__ unsigned           s_state[4];         // prefix, mask, kk, gt
    __shared__ float              s_redf[32];
    __shared__ unsigned           s_wc[32];
    __shared__ unsigned long long s_wf[32];
    __shared__ int                s_B;
    __shared__ unsigned           s_kk, s_cnt;
    __shared__ unsigned long long s_above;
    __shared__ float              s_sl1, s_ps;
    __shared__ int                s_pn;
    __shared__ unsigned           s_last;

    const int n   = blockIdx.x;
    const int tid = threadIdx.x;
    const int wid = tid >> 5, lane = tid & 31;
    const int dl  = domain_label[n];
    float rowval = 0.f;

    if (dl == 0) {
        if (tid == 0) {
            float ps = 0.f; int pp = 0;
#pragma unroll
            for (int q = 0; q < 9; q++) { ps += g_partcon[n * 16 + q]; pp += g_partpos[n * 16 + q]; }
            s_ps = ps; s_pn = pp;
            s_B = -2; s_cnt = 0u;
            s_state[0] = 0u; s_state[1] = 0u; s_state[3] = 0u;
        }
        __syncthreads();
        int pos = s_pn;

        if (pos > 0) {
            // ---- masked smooth-L1, vectorized with group skip ----
            const int4*   G  = (const int4*)(glabel + (size_t)n * A_);
            const float4* PL = (const float4*)(ploc + (size_t)n * 4 * A_);
            const float4* GL = (const float4*)(gloc + (size_t)n * 4 * A_);
            const float4* DB = (const float4*)dboxes;
            float sl1 = 0.f;
#pragma unroll
            for (int chunk = 0; chunk < 3; chunk++) {
                int grp = chunk * 1024 + tid;
                if (grp < A4_) {
                    int4 g = G[grp];
                    bool m0 = g.x > 0, m1 = g.y > 0, m2 = g.z > 0, m3 = g.w > 0;
                    if (m0 | m1 | m2 | m3) {
                        float4 plx = PL[0 * A4_ + grp], ply = PL[1 * A4_ + grp];
                        float4 plw = PL[2 * A4_ + grp], plh = PL[3 * A4_ + grp];
                        float4 glx = GL[0 * A4_ + grp], gly = GL[1 * A4_ + grp];
                        float4 glw = GL[2 * A4_ + grp], glh = GL[3 * A4_ + grp];
                        float4 dbx = DB[0 * A4_ + grp], dby = DB[1 * A4_ + grp];
                        float4 dbw = DB[2 * A4_ + grp], dbh = DB[3 * A4_ + grp];
#define SL1_LANE(M, PX, PY, PW, PH, GX, GY, GW, GH, DX, DY, DW, DH)           \
                        if (M) {                                              \
                            float v0 = 10.f * (GX - DX) / DW;                 \
                            float v1 = 10.f * (GY - DY) / DH;                 \
                            float v2 = 5.f * __logf(GW / DW);                 \
                            float v3 = 5.f * __logf(GH / DH);                 \
                            float d0 = PX - v0, d1 = PY - v1;                 \
                            float d2 = PW - v2, d3 = PH - v3;                 \
                            float ad;                                         \
                            ad = fabsf(d0); sl1 += (ad < 1.f) ? 0.5f*d0*d0 : ad-0.5f; \
                            ad = fabsf(d1); sl1 += (ad < 1.f) ? 0.5f*d1*d1 : ad-0.5f; \
                            ad = fabsf(d2); sl1 += (ad < 1.f) ? 0.5f*d2*d2 : ad-0.5f; \
                            ad = fabsf(d3); sl1 += (ad < 1.f) ? 0.5f*d3*d3 : ad-0.5f; \
                        }
                        SL1_LANE(m0, plx.x, ply.x, plw.x, plh.x, glx.x, gly.x, glw.x, glh.x, dbx.x, dby.x, dbw.x, dbh.x)
                        SL1_LANE(m1, plx.y, ply.y, plw.y, plh.y, glx.y, gly.y, glw.y, glh.y, dbx.y, dby.y, dbw.y, dbh.y)
                        SL1_LANE(m2, plx.z, ply.z, plw.z, plh.z, glx.z, gly.z, glw.z, glh.z, dbx.z, dby.z, dbw.z, dbh.z)
                        SL1_LANE(m3, plx.w, ply.w, plw.w, plh.w, glx.w, gly.w, glw.w, glh.w, dbx.w, dby.w, dbw.w, dbh.w)
#undef SL1_LANE
                    }
                }
            }
            for (int o = 16; o > 0; o >>= 1) sl1 += __shfl_down_sync(0xffffffffu, sl1, o);
            if (lane == 0) s_redf[wid] = sl1;
            __syncthreads();
            if (tid == 0) {
                float t = 0.f;
#pragma unroll
                for (int q = 0; q < 32; q++) t += s_redf[q];
                s_sl1 = t;
            }

            // ---- suffix scan of bucket hist/sums; find boundary bucket ----
            const int k = (3 * pos > A_) ? A_ : 3 * pos;
            uint2      hh = ((const uint2*)(g_hist + (size_t)n * NB_))[tid];
            ulonglong2 ff = ((const ulonglong2*)(g_bsumfx + (size_t)n * NB_))[tid];
            unsigned           c = hh.x + hh.y;
            unsigned long long f = ff.x + ff.y;
#pragma unroll
            for (int o = 1; o < 32; o <<= 1) {
                unsigned           uc = __shfl_down_sync(0xffffffffu, c, o);
                unsigned long long uf = __shfl_down_sync(0xffffffffu, f, o);
                if (lane + o < 32) { c += uc; f += uf; }
            }
            if (lane == 0) { s_wc[wid] = c; s_wf[wid] = f; }
            __syncthreads();
            if (tid < 32) {
                unsigned           cc = s_wc[tid];
                unsigned long long fw = s_wf[tid];
#pragma unroll
                for (int o = 1; o < 32; o <<= 1) {
                    unsigned           uc = __shfl_down_sync(0xffffffffu, cc, o);
                    unsigned long long uf = __shfl_down_sync(0xffffffffu, fw, o);
                    if (tid + o < 32) { cc += uc; fw += uf; }
                }
                s_wc[tid] = cc; s_wf[tid] = fw;
            }
            __syncthreads();
            unsigned           hi  = (wid < 31) ? s_wc[wid + 1] : 0u;
            unsigned long long hif = (wid < 31) ? s_wf[wid + 1] : 0ull;
            unsigned           suf0  = c + hi;    // suffix incl from bin 2*tid
            unsigned long long suf0f = f + hif;
            {   // bin 2*tid
                unsigned suf = suf0, h = hh.x, gtc = suf - h;
                if (h && gtc < (unsigned)k && suf >= (unsigned)k) {
                    s_B = 2 * tid; s_kk = (unsigned)k - gtc; s_above = suf0f - ff.x;
                }
            }
            {   // bin 2*tid+1
                unsigned suf = suf0 - hh.x, h = hh.y, gtc = suf - h;
                if (h && gtc < (unsigned)k && suf >= (unsigned)k) {
                    s_B = 2 * tid + 1; s_kk = (unsigned)k - gtc; s_above = suf0f - ff.x - ff.y;
                }
            }
            if (tid == 0 && suf0 < (unsigned)k) { s_B = -1; s_above = suf0f; }  // take everything
            __syncthreads();

            float topk = 0.f;
            if (s_B == -1) {
                topk = (float)((double)s_above * (1.0 / (double)FXS));
            } else {
                const int B = s_B;
                const unsigned kk = s_kk;
                // ---- single scan: collect boundary-bucket elements ----
                const uint4* gc = (const uint4*)g_con + (size_t)n * A4_;
                for (int grp = tid; grp < A4_; grp += 1024) {
                    uint4 x = __ldcg(gc + grp);
                    if ((x.x >> 21) == (unsigned)B) { unsigned p = atomicAdd(&s_cnt, 1u); s_list[p] = x.x; }
                    if ((x.y >> 21) == (unsigned)B) { unsigned p = atomicAdd(&s_cnt, 1u); s_list[p] = x.y; }
                    if ((x.z >> 21) == (unsigned)B) { unsigned p = atomicAdd(&s_cnt, 1u); s_list[p] = x.z; }
                    if ((x.w >> 21) == (unsigned)B) { unsigned p = atomicAdd(&s_cnt, 1u); s_list[p] = x.w; }
                }
                __syncthreads();
                const unsigned cnt = s_cnt;
                const float above = (float)((double)s_above * (1.0 / (double)FXS));

                if (kk >= cnt) {
                    float sl = 0.f;
                    for (unsigned i = tid; i < cnt; i += 1024) sl += __uint_as_float(s_list[i]);
                    for (int o = 16; o > 0; o >>= 1) sl += __shfl_down_sync(0xffffffffu, sl, o);
                    if (lane == 0) s_redf[wid] = sl;
                    __syncthreads();
                    if (tid == 0) {
                        float t = 0.f;
#pragma unroll
                        for (int q = 0; q < 32; q++) t += s_redf[q];
                        topk = above + t;
                    }
                } else {
                    // exact radix select (kk-th largest) over the small list
                    if (tid == 0) s_state[2] = kk;
                    __syncthreads();
#pragma unroll
                    for (int shift = 24; shift >= 0; shift -= 8) {
                        if (tid < 256) s_hist[tid] = 0u;
                        __syncthreads();
                        unsigned pref = s_state[0], msk = s_state[1];
                        for (unsigned i = tid; i < cnt; i += 1024) {
                            unsigned x = s_list[i];
                            if ((x & msk) == pref) atomicAdd(&s_hist[(x >> shift) & 255u], 1u);
                        }
                        __syncthreads();
                        if (tid < 32) {
                            unsigned base = (unsigned)tid << 3;
                            unsigned lh[8], ls[8];
#pragma unroll
                            for (int q = 0; q < 8; q++) lh[q] = s_hist[base + q];
                            unsigned run = 0;
#pragma unroll
                            for (int q = 7; q >= 0; q--) { run += lh[q]; ls[q] = run; }
                            unsigned incl = run;
#pragma unroll
                            for (int o = 1; o < 32; o <<= 1) {
                                unsigned v = __shfl_down_sync(0xffffffffu, incl, o);
                                if (tid + o < 32) incl += v;
                            }
                            unsigned exh = incl - run;
                            unsigned kkk = s_state[2];
#pragma unroll
                            for (int q = 0; q < 8; q++) {
                                unsigned suf = exh + ls[q];
                                unsigned gtc = suf - lh[q];
                                if (gtc < kkk && suf >= kkk) {
                                    s_state[0] |= (base + q) << shift;
                                    s_state[1] |= 0xFFu << shift;
                                    s_state[2] = kkk - gtc;
                                    s_state[3] += gtc;
                                }
                            }
                        }
                        __syncthreads();
                    }
                    unsigned T    = s_state[0];
                    unsigned ties = s_state[2];
                    float sgt = 0.f;
                    for (unsigned i = tid; i < cnt; i += 1024) {
                        unsigned x = s_list[i];
                        if (x > T) sgt += __uint_as_float(x);
                    }
                    for (int o = 16; o > 0; o >>= 1) sgt += __shfl_down_sync(0xffffffffu, sgt, o);
                    if (lane == 0) s_redf[wid] = sgt;
                    __syncthreads();
                    if (tid == 0) {
                        float t = 0.f;
#pragma unroll
                        for (int q = 0; q < 32; q++) t += s_redf[q];
                        topk = above + t + (float)ties * __uint_as_float(T);
                    }
                }
            }
            if (tid == 0) rowval = (s_ps + s_sl1 + topk) / (float)pos;
        }
    }

    if (tid == 0) {
        g_row[n] = rowval;
        __threadfence();
        unsigned old = atomicAdd(&g_count, 1u);
        s_last = (old == N_ - 1u) ? 1u : 0u;
    }
    __syncthreads();

    if (s_last) {
        __threadfence();
        float v = (tid < N_) ? g_row[tid] : 0.f;
        for (int o = 16; o > 0; o >>= 1) v += __shfl_down_sync(0xffffffffu, v, o);
        if (lane == 0) s_redf[wid] = v;
        __syncthreads();
        if (tid == 0) {
            float t = 0.f;
#pragma unroll
            for (int q = 0; q < 4; q++) t += s_redf[q];   // warps 0-3 held 128 rows
            out[0] = t / (float)N_;
            g_count = 0u;   // reset for next graph replay
        }
    }
}

extern "C" void kernel_launch(void* const* d_in, const int* in_sizes, int n_in,
                              void* d_out, int out_size)
{
    const float* ploc         = (const float*)d_in[0];
    const float* plabel       = (const float*)d_in[1];
    const float* gloc         = (const float*)d_in[2];
    const int*   glabel       = (const int*)  d_in[3];
    const int*   domain_label = (const int*)  d_in[4];
    const float* dboxes       = (const float*)d_in[5];
    float* out = (float*)d_out;

    void *hp = nullptr, *fp = nullptr;
    cudaGetSymbolAddress(&hp, g_hist);
    cudaGetSymbolAddress(&fp, g_bsumfx);
    cudaMemsetAsync(hp, 0, (size_t)N_ * NB_ * sizeof(unsigned));
    cudaMemsetAsync(fp, 0, (size_t)N_ * NB_ * sizeof(unsigned long long));

    dim3 g1(9, N_);
    kA_focal<<<g1, 256>>>(plabel, glabel, domain_label);
    kT_tail<<<N_, 1024>>>(ploc, gloc, glabel, domain_label, dboxes, out);
}

// round 8
// speedup vs baseline: 1.1353x; 1.1353x over previous
#include <cuda_runtime.h>
#include <cuda_bf16.h>
#include <cstdint>

#define N_ 128
#define C_ 81
#define A_ 8732
#define A4_ 2183          // A_/4 exactly
#define LISTCAP 2048

// Scratch (device globals — no allocations allowed)
__device__ unsigned g_con[N_ * A_];        // focal bits (dl==0 rows), positives = 0u
__device__ float    g_partcon[N_ * 16];
__device__ int      g_partpos[N_ * 16];
__device__ float    g_row[N_];
__device__ unsigned g_count;               // self-resetting

// ---------------------------------------------------------------------------
// Kernel A: focal loss per anchor (clean R5 version — at its traffic floor).
// grid = (9, N), block = 256. Whole block exits when domain_label != 0.
// ---------------------------------------------------------------------------
__global__ __launch_bounds__(256, 8) void kA_focal(const float* __restrict__ plabel,
                                                   const int*   __restrict__ glabel,
                                                   const int*   __restrict__ domain_label)
{
    const int n = blockIdx.y;
    if (domain_label[n] != 0) return;

    int idx = blockIdx.x * 256 + threadIdx.x;
    bool valid = (idx < A4_);
    int ii = valid ? idx : (A4_ - 1);

    const float4* P = (const float4*)(plabel + (size_t)n * C_ * A_) + ii;
    int4 g = ((const int4*)(glabel + (size_t)n * A_))[ii];

    float4 s  = make_float4(0.f, 0.f, 0.f, 0.f);
    float4 xg = make_float4(0.f, 0.f, 0.f, 0.f);
#pragma unroll 3
    for (int c = 0; c < C_; c++) {
        float4 x = __ldcs(P);
        P += A4_;
        if (c == g.x) xg.x = x.x;
        if (c == g.y) xg.y = x.y;
        if (c == g.z) xg.z = x.z;
        if (c == g.w) xg.w = x.w;
        s.x += __expf(x.x); s.y += __expf(x.y);
        s.z += __expf(x.z); s.w += __expf(x.w);
    }

    float lp0 = xg.x - __logf(s.x), lp1 = xg.y - __logf(s.y);
    float lp2 = xg.z - __logf(s.z), lp3 = xg.w - __logf(s.w);
    float o0 = 1.f - __expf(lp0), o1 = 1.f - __expf(lp1);
    float o2 = 1.f - __expf(lp2), o3 = 1.f - __expf(lp3);
    float c0 = -0.25f * o0 * o0 * lp0;
    float c1 = -0.25f * o1 * o1 * lp1;
    float c2 = -0.25f * o2 * o2 * lp2;
    float c3 = -0.25f * o3 * o3 * lp3;

    bool m0 = g.x > 0, m1 = g.y > 0, m2 = g.z > 0, m3 = g.w > 0;

    uint4 cw;
    cw.x = m0 ? 0u : __float_as_uint(c0);
    cw.y = m1 ? 0u : __float_as_uint(c1);
    cw.z = m2 ? 0u : __float_as_uint(c2);
    cw.w = m3 ? 0u : __float_as_uint(c3);
    ((uint4*)g_con)[(size_t)n * A4_ + ii] = cw;

    float contrib = 0.f;
    int pc = 0;
    if (valid) {
        if (m0) { contrib += c0; pc++; }
        if (m1) { contrib += c1; pc++; }
        if (m2) { contrib += c2; pc++; }
        if (m3) { contrib += c3; pc++; }
    }
    for (int o = 16; o > 0; o >>= 1) {
        contrib += __shfl_down_sync(0xffffffffu, contrib, o);
        pc      += __shfl_down_sync(0xffffffffu, pc, o);
    }
    __shared__ float sw[8];
    __shared__ int   swp[8];
    int wid = threadIdx.x >> 5, lane = threadIdx.x & 31;
    if (lane == 0) { sw[wid] = contrib; swp[wid] = pc; }
    __syncthreads();
    if (threadIdx.x == 0) {
        float t = 0.f; int tp = 0;
#pragma unroll
        for (int j = 0; j < 8; j++) { t += sw[j]; tp += swp[j]; }
        g_partcon[n * 16 + blockIdx.x] = t;
        g_partpos[n * 16 + blockIdx.x] = tp;
    }
}

// ---------------------------------------------------------------------------
// Kernel T: per-row tail. g_con is L2-resident (4.5 MB << 126 MB L2).
//   pass 1: 2048-bin count histogram (smem, 4-way replicated) + suffix scan
//           -> boundary bucket B, kk, cnt[B]
//   pass 2: exact float sum of buckets > B; collect bucket-B elems to smem
//   micro radix-select over the short list -> exact tie threshold
// grid = N_, block = 1024. Last-arriving CTA computes the mean.
// ---------------------------------------------------------------------------
__global__ __launch_bounds__(1024) void kT_tail(const float* __restrict__ ploc,
                                                const float* __restrict__ gloc,
                                                const int*   __restrict__ glabel,
                                                const int*   __restrict__ domain_label,
                                                const float* __restrict__ dboxes,
                                                float* __restrict__ out)
{
    __shared__ unsigned s_hist[8192];      // 4 replicas x 2048 bins (32 KB)
    __shared__ unsigned s_list[LISTCAP];   // 8 KB
    __shared__ unsigned s_wc[32];
    __shared__ float    s_redf[32];
    __shared__ unsigned s_state[4];        // prefix, mask, kk, gt (micro select)
    __shared__ int      s_B;
    __shared__ unsigned s_kk, s_cntB, s_cnt;
    __shared__ float    s_sl1, s_ps, s_above;
    __shared__ int      s_pn;
    __shared__ unsigned s_last;

    const int n   = blockIdx.x;
    const int tid = threadIdx.x;
    const int wid = tid >> 5, lane = tid & 31;
    const int dl  = domain_label[n];
    float rowval = 0.f;

    if (dl == 0) {
        if (tid == 0) {
            float ps = 0.f; int pp = 0;
#pragma unroll
            for (int q = 0; q < 9; q++) { ps += g_partcon[n * 16 + q]; pp += g_partpos[n * 16 + q]; }
            s_ps = ps; s_pn = pp;
            s_B = -2; s_cnt = 0u;
            s_state[0] = 0u; s_state[1] = 0u; s_state[3] = 0u;
        }
        // zero histogram replicas while tid0 works
#pragma unroll
        for (int q = 0; q < 8; q++) s_hist[q * 1024 + tid] = 0u;
        __syncthreads();
        const int pos = s_pn;

        if (pos > 0) {
            // ================= masked smooth-L1 =================
            const int4*   G  = (const int4*)(glabel + (size_t)n * A_);
            const float4* PL = (const float4*)(ploc + (size_t)n * 4 * A_);
            const float4* GL = (const float4*)(gloc + (size_t)n * 4 * A_);
            const float4* DB = (const float4*)dboxes;
            float sl1 = 0.f;
#pragma unroll
            for (int chunk = 0; chunk < 3; chunk++) {
                int grp = chunk * 1024 + tid;
                if (grp < A4_) {
                    int4 g = G[grp];
                    bool m0 = g.x > 0, m1 = g.y > 0, m2 = g.z > 0, m3 = g.w > 0;
                    if (m0 | m1 | m2 | m3) {
                        float4 plx = PL[0 * A4_ + grp], ply = PL[1 * A4_ + grp];
                        float4 plw = PL[2 * A4_ + grp], plh = PL[3 * A4_ + grp];
                        float4 glx = GL[0 * A4_ + grp], gly = GL[1 * A4_ + grp];
                        float4 glw = GL[2 * A4_ + grp], glh = GL[3 * A4_ + grp];
                        float4 dbx = DB[0 * A4_ + grp], dby = DB[1 * A4_ + grp];
                        float4 dbw = DB[2 * A4_ + grp], dbh = DB[3 * A4_ + grp];
#define SL1_LANE(M, PX, PY, PW, PH, GX, GY, GW, GH, DX, DY, DW, DH)           \
                        if (M) {                                              \
                            float v0 = 10.f * (GX - DX) / DW;                 \
                            float v1 = 10.f * (GY - DY) / DH;                 \
                            float v2 = 5.f * __logf(GW / DW);                 \
                            float v3 = 5.f * __logf(GH / DH);                 \
                            float d0 = PX - v0, d1 = PY - v1;                 \
                            float d2 = PW - v2, d3 = PH - v3;                 \
                            float ad;                                         \
                            ad = fabsf(d0); sl1 += (ad < 1.f) ? 0.5f*d0*d0 : ad-0.5f; \
                            ad = fabsf(d1); sl1 += (ad < 1.f) ? 0.5f*d1*d1 : ad-0.5f; \
                            ad = fabsf(d2); sl1 += (ad < 1.f) ? 0.5f*d2*d2 : ad-0.5f; \
                            ad = fabsf(d3); sl1 += (ad < 1.f) ? 0.5f*d3*d3 : ad-0.5f; \
                        }
                        SL1_LANE(m0, plx.x, ply.x, plw.x, plh.x, glx.x, gly.x, glw.x, glh.x, dbx.x, dby.x, dbw.x, dbh.x)
                        SL1_LANE(m1, plx.y, ply.y, plw.y, plh.y, glx.y, gly.y, glw.y, glh.y, dbx.y, dby.y, dbw.y, dbh.y)
                        SL1_LANE(m2, plx.z, ply.z, plw.z, plh.z, glx.z, gly.z, glw.z, glh.z, dbx.z, dby.z, dbw.z, dbh.z)
                        SL1_LANE(m3, plx.w, ply.w, plw.w, plh.w, glx.w, gly.w, glw.w, glh.w, dbx.w, dby.w, dbw.w, dbh.w)
#undef SL1_LANE
                    }
                }
            }
            for (int o = 16; o > 0; o >>= 1) sl1 += __shfl_down_sync(0xffffffffu, sl1, o);
            if (lane == 0) s_redf[wid] = sl1;
            __syncthreads();
            if (tid == 0) {
                float t = 0.f;
#pragma unroll
                for (int q = 0; q < 32; q++) t += s_redf[q];
                s_sl1 = t;
            }

            // ================= pass 1: histogram build =================
            const uint4* gc = (const uint4*)g_con + (size_t)n * A4_;
            const unsigned hb = ((unsigned)wid & 3u) << 11;
            for (int grp = tid; grp < A4_; grp += 1024) {
                uint4 x = __ldcg(gc + grp);
                atomicAdd(&s_hist[hb + (x.x >> 21)], 1u);
                atomicAdd(&s_hist[hb + (x.y >> 21)], 1u);
                atomicAdd(&s_hist[hb + (x.z >> 21)], 1u);
                atomicAdd(&s_hist[hb + (x.w >> 21)], 1u);
            }
            __syncthreads();

            // ---- suffix scan (2 bins/thread) + boundary bucket ----
            const int k = (3 * pos > A_) ? A_ : 3 * pos;
            unsigned h0 = s_hist[2 * tid]     + s_hist[2048 + 2 * tid]
                        + s_hist[4096 + 2 * tid] + s_hist[6144 + 2 * tid];
            unsigned h1 = s_hist[2 * tid + 1]     + s_hist[2048 + 2 * tid + 1]
                        + s_hist[4096 + 2 * tid + 1] + s_hist[6144 + 2 * tid + 1];
            unsigned c = h0 + h1;
#pragma unroll
            for (int o = 1; o < 32; o <<= 1) {
                unsigned uc = __shfl_down_sync(0xffffffffu, c, o);
                if (lane + o < 32) c += uc;
            }
            if (lane == 0) s_wc[wid] = c;
            __syncthreads();
            if (tid < 32) {
                unsigned cc = s_wc[tid];
#pragma unroll
                for (int o = 1; o < 32; o <<= 1) {
                    unsigned uc = __shfl_down_sync(0xffffffffu, cc, o);
                    if (tid + o < 32) cc += uc;
                }
                s_wc[tid] = cc;
            }
            __syncthreads();
            {
                unsigned hi   = (wid < 31) ? s_wc[wid + 1] : 0u;
                unsigned suf0 = c + hi;                 // suffix incl from bin 2*tid
                unsigned gtc0 = suf0 - h0;
                if (h0 && gtc0 < (unsigned)k && suf0 >= (unsigned)k) {
                    s_B = 2 * tid; s_kk = (unsigned)k - gtc0; s_cntB = h0;
                }
                unsigned suf1 = suf0 - h0;
                unsigned gtc1 = suf1 - h1;
                if (h1 && gtc1 < (unsigned)k && suf1 >= (unsigned)k) {
                    s_B = 2 * tid + 1; s_kk = (unsigned)k - gtc1; s_cntB = h1;
                }
            }
            __syncthreads();

            const int      B    = s_B;
            const unsigned kk   = s_kk;
            const unsigned cntB = s_cntB;
            const bool     fits = (cntB <= (unsigned)LISTCAP);

            // ================= pass 2: sum above + collect boundary ====
            float above = 0.f;
            for (int grp = tid; grp < A4_; grp += 1024) {
                uint4 x = __ldcg(gc + grp);
                int b0 = (int)(x.x >> 21), b1 = (int)(x.y >> 21);
                int b2 = (int)(x.z >> 21), b3 = (int)(x.w >> 21);
                if (b0 > B) above += __uint_as_float(x.x);
                else if (fits && b0 == B) { unsigned p = atomicAdd(&s_cnt, 1u); s_list[p] = x.x; }
                if (b1 > B) above += __uint_as_float(x.y);
                else if (fits && b1 == B) { unsigned p = atomicAdd(&s_cnt, 1u); s_list[p] = x.y; }
                if (b2 > B) above += __uint_as_float(x.z);
                else if (fits && b2 == B) { unsigned p = atomicAdd(&s_cnt, 1u); s_list[p] = x.z; }
                if (b3 > B) above += __uint_as_float(x.w);
                else if (fits && b3 == B) { unsigned p = atomicAdd(&s_cnt, 1u); s_list[p] = x.w; }
            }
            for (int o = 16; o > 0; o >>= 1) above += __shfl_down_sync(0xffffffffu, above, o);
            if (lane == 0) s_redf[wid] = above;
            __syncthreads();
            if (tid == 0) {
                float t = 0.f;
#pragma unroll
                for (int q = 0; q < 32; q++) t += s_redf[q];
                s_above = t;
            }
            __syncthreads();

            float topk = 0.f;
            if (fits) {
                const unsigned cnt = s_cnt;     // == cntB
                if (kk >= cnt) {
                    float sl = 0.f;
                    for (unsigned i = tid; i < cnt; i += 1024) sl += __uint_as_float(s_list[i]);
                    for (int o = 16; o > 0; o >>= 1) sl += __shfl_down_sync(0xffffffffu, sl, o);
                    if (lane == 0) s_redf[wid] = sl;
                    __syncthreads();
                    if (tid == 0) {
                        float t = 0.f;
#pragma unroll
                        for (int q = 0; q < 32; q++) t += s_redf[q];
                        topk = s_above + t;
                    }
                } else {
                    // micro radix select (kk-th largest within the short list)
                    if (tid == 0) s_state[2] = kk;
                    __syncthreads();
#pragma unroll
                    for (int shift = 24; shift >= 0; shift -= 8) {
                        if (tid < 256) s_hist[tid] = 0u;
                        __syncthreads();
                        unsigned pref = s_state[0], msk = s_state[1];
                        for (unsigned i = tid; i < cnt; i += 1024) {
                            unsigned x = s_list[i];
                            if ((x & msk) == pref) atomicAdd(&s_hist[(x >> shift) & 255u], 1u);
                        }
                        __syncthreads();
                        if (tid < 32) {
                            unsigned base = (unsigned)tid << 3;
                            unsigned lh[8], ls[8];
#pragma unroll
                            for (int q = 0; q < 8; q++) lh[q] = s_hist[base + q];
                            unsigned run = 0;
#pragma unroll
                            for (int q = 7; q >= 0; q--) { run += lh[q]; ls[q] = run; }
                            unsigned incl = run;
#pragma unroll
                            for (int o = 1; o < 32; o <<= 1) {
                                unsigned v = __shfl_down_sync(0xffffffffu, incl, o);
                                if (tid + o < 32) incl += v;
                            }
                            unsigned exh = incl - run;
                            unsigned kkk = s_state[2];
#pragma unroll
                            for (int q = 0; q < 8; q++) {
                                unsigned suf = exh + ls[q];
                                unsigned gtc = suf - lh[q];
                                if (gtc < kkk && suf >= kkk) {
                                    s_state[0] |= (base + q) << shift;
                                    s_state[1] |= 0xFFu << shift;
                                    s_state[2] = kkk - gtc;
                                    s_state[3] += gtc;
                                }
                            }
                        }
                        __syncthreads();
                    }
                    unsigned T    = s_state[0];
                    unsigned ties = s_state[2];
                    float sgt = 0.f;
                    for (unsigned i = tid; i < cnt; i += 1024) {
                        unsigned x = s_list[i];
                        if (x > T) sgt += __uint_as_float(x);
                    }
                    for (int o = 16; o > 0; o >>= 1) sgt += __shfl_down_sync(0xffffffffu, sgt, o);
                    if (lane == 0) s_redf[wid] = sgt;
                    __syncthreads();
                    if (tid == 0) {
                        float t = 0.f;
#pragma unroll
                        for (int q = 0; q < 32; q++) t += s_redf[q];
                        topk = s_above + t + (float)ties * __uint_as_float(T);
                    }
                }
            } else {
                // fallback (boundary bucket too large): full radix select over gmem
                if (tid == 0) { s_state[0] = 0u; s_state[1] = 0u; s_state[2] = (unsigned)k; s_state[3] = 0u; }
                __syncthreads();
#pragma unroll
                for (int shift = 24; shift >= 0; shift -= 8) {
                    if (tid < 256) s_hist[tid] = 0u;
                    __syncthreads();
                    unsigned pref = s_state[0], msk = s_state[1];
                    for (int grp = tid; grp < A4_; grp += 1024) {
                        uint4 x = __ldcg(gc + grp);
                        if ((x.x & msk) == pref) atomicAdd(&s_hist[(x.x >> shift) & 255u], 1u);
                        if ((x.y & msk) == pref) atomicAdd(&s_hist[(x.y >> shift) & 255u], 1u);
                        if ((x.z & msk) == pref) atomicAdd(&s_hist[(x.z >> shift) & 255u], 1u);
                        if ((x.w & msk) == pref) atomicAdd(&s_hist[(x.w >> shift) & 255u], 1u);
                    }
                    __syncthreads();
                    if (tid < 32) {
                        unsigned base = (unsigned)tid << 3;
                        unsigned lh[8], ls[8];
#pragma unroll
                        for (int q = 0; q < 8; q++) lh[q] = s_hist[base + q];
                        unsigned run = 0;
#pragma unroll
                        for (int q = 7; q >= 0; q--) { run += lh[q]; ls[q] = run; }
                        unsigned incl = run;
#pragma unroll
                        for (int o = 1; o < 32; o <<= 1) {
                            unsigned v = __shfl_down_sync(0xffffffffu, incl, o);
                            if (tid + o < 32) incl += v;
                        }
                        unsigned exh = incl - run;
                        unsigned kkk = s_state[2];
#pragma unroll
                        for (int q = 0; q < 8; q++) {
                            unsigned suf = exh + ls[q];
                            unsigned gtc = suf - lh[q];
                            if (gtc < kkk && suf >= kkk) {
                                s_state[0] |= (base + q) << shift;
                                s_state[1] |= 0xFFu << shift;
                                s_state[2] = kkk - gtc;
                                s_state[3] += gtc;
                            }
                        }
                    }
                    __syncthreads();
                }
                unsigned T    = s_state[0];
                unsigned ties = s_state[2];
                float sgt = 0.f;
                for (int grp = tid; grp < A4_; grp += 1024) {
                    uint4 x = __ldcg(gc + grp);
                    if (x.x > T) sgt += __uint_as_float(x.x);
                    if (x.y > T) sgt += __uint_as_float(x.y);
                    if (x.z > T) sgt += __uint_as_float(x.z);
                    if (x.w > T) sgt += __uint_as_float(x.w);
                }
                for (int o = 16; o > 0; o >>= 1) sgt += __shfl_down_sync(0xffffffffu, sgt, o);
                if (lane == 0) s_redf[wid] = sgt;
                __syncthreads();
                if (tid == 0) {
                    float t = 0.f;
#pragma unroll
                    for (int q = 0; q < 32; q++) t += s_redf[q];
                    topk = t + (float)ties * __uint_as_float(T);
                }
            }

            if (tid == 0) rowval = (s_ps + s_sl1 + topk) / (float)pos;
        }
    }

    if (tid == 0) {
        g_row[n] = rowval;
        __threadfence();
        unsigned old = atomicAdd(&g_count, 1u);
        s_last = (old == N_ - 1u) ? 1u : 0u;
    }
    __syncthreads();

    if (s_last) {
        __threadfence();
        float v = (tid < N_) ? g_row[tid] : 0.f;
        for (int o = 16; o > 0; o >>= 1) v += __shfl_down_sync(0xffffffffu, v, o);
        if (lane == 0) s_redf[wid] = v;
        __syncthreads();
        if (tid == 0) {
            float t = 0.f;
#pragma unroll
            for (int q = 0; q < 4; q++) t += s_redf[q];   // warps 0-3 held 128 rows
            out[0] = t / (float)N_;
            g_count = 0u;   // reset for next graph replay
        }
    }
}

extern "C" void kernel_launch(void* const* d_in, const int* in_sizes, int n_in,
                              void* d_out, int out_size)
{
    const float* ploc         = (const float*)d_in[0];
    const float* plabel       = (const float*)d_in[1];
    const float* gloc         = (const float*)d_in[2];
    const int*   glabel       = (const int*)  d_in[3];
    const int*   domain_label = (const int*)  d_in[4];
    const float* dboxes       = (const float*)d_in[5];
    float* out = (float*)d_out;

    dim3 g1(9, N_);
    kA_focal<<<g1, 256>>>(plabel, glabel, domain_label);
    kT_tail<<<N_, 1024>>>(ploc, gloc, glabel, domain_label, dboxes, out);
}

// round 9
// speedup vs baseline: 1.2267x; 1.0804x over previous
#include <cuda_runtime.h>
#include <cuda_bf16.h>
#include <cstdint>

#define N_ 128
#define C_ 81
#define A_ 8732
#define A4_ 2183          // A_/4 exactly
#define NB 4096           // bins per histogram level (12 bits)
#define DYN_BYTES ((8736 + 4 * NB) * 4)   // s_con + 4 hist replicas = 100480 B

// Scratch (device globals — no allocations allowed)
__device__ unsigned g_con[N_ * A_];        // focal bits (dl==0 rows), positives = 0u
__device__ float    g_partcon[N_ * 16];
__device__ int      g_partpos[N_ * 16];
__device__ float    g_row[N_];
__device__ unsigned g_count;               // self-resetting

// ---------------------------------------------------------------------------
// Kernel A: focal loss per anchor (at its traffic floor — unchanged).
// grid = (9, N), block = 256. Whole block exits when domain_label != 0.
// ---------------------------------------------------------------------------
__global__ __launch_bounds__(256, 8) void kA_focal(const float* __restrict__ plabel,
                                                   const int*   __restrict__ glabel,
                                                   const int*   __restrict__ domain_label)
{
    const int n = blockIdx.y;
    if (domain_label[n] != 0) return;

    int idx = blockIdx.x * 256 + threadIdx.x;
    bool valid = (idx < A4_);
    int ii = valid ? idx : (A4_ - 1);

    const float4* P = (const float4*)(plabel + (size_t)n * C_ * A_) + ii;
    int4 g = ((const int4*)(glabel + (size_t)n * A_))[ii];

    float4 s  = make_float4(0.f, 0.f, 0.f, 0.f);
    float4 xg = make_float4(0.f, 0.f, 0.f, 0.f);
#pragma unroll 3
    for (int c = 0; c < C_; c++) {
        float4 x = __ldcs(P);
        P += A4_;
        if (c == g.x) xg.x = x.x;
        if (c == g.y) xg.y = x.y;
        if (c == g.z) xg.z = x.z;
        if (c == g.w) xg.w = x.w;
        s.x += __expf(x.x); s.y += __expf(x.y);
        s.z += __expf(x.z); s.w += __expf(x.w);
    }

    float lp0 = xg.x - __logf(s.x), lp1 = xg.y - __logf(s.y);
    float lp2 = xg.z - __logf(s.z), lp3 = xg.w - __logf(s.w);
    float o0 = 1.f - __expf(lp0), o1 = 1.f - __expf(lp1);
    float o2 = 1.f - __expf(lp2), o3 = 1.f - __expf(lp3);
    float c0 = -0.25f * o0 * o0 * lp0;
    float c1 = -0.25f * o1 * o1 * lp1;
    float c2 = -0.25f * o2 * o2 * lp2;
    float c3 = -0.25f * o3 * o3 * lp3;

    bool m0 = g.x > 0, m1 = g.y > 0, m2 = g.z > 0, m3 = g.w > 0;

    uint4 cw;
    cw.x = m0 ? 0u : __float_as_uint(c0);
    cw.y = m1 ? 0u : __float_as_uint(c1);
    cw.z = m2 ? 0u : __float_as_uint(c2);
    cw.w = m3 ? 0u : __float_as_uint(c3);
    ((uint4*)g_con)[(size_t)n * A4_ + ii] = cw;

    float contrib = 0.f;
    int pc = 0;
    if (valid) {
        if (m0) { contrib += c0; pc++; }
        if (m1) { contrib += c1; pc++; }
        if (m2) { contrib += c2; pc++; }
        if (m3) { contrib += c3; pc++; }
    }
    for (int o = 16; o > 0; o >>= 1) {
        contrib += __shfl_down_sync(0xffffffffu, contrib, o);
        pc      += __shfl_down_sync(0xffffffffu, pc, o);
    }
    __shared__ float sw[8];
    __shared__ int   swp[8];
    int wid = threadIdx.x >> 5, lane = threadIdx.x & 31;
    if (lane == 0) { sw[wid] = contrib; swp[wid] = pc; }
    __syncthreads();
    if (threadIdx.x == 0) {
        float t = 0.f; int tp = 0;
#pragma unroll
        for (int j = 0; j < 8; j++) { t += sw[j]; tp += swp[j]; }
        g_partcon[n * 16 + blockIdx.x] = t;
        g_partpos[n * 16 + blockIdx.x] = tp;
    }
}

// ---------------------------------------------------------------------------
// Kernel T: per-row tail, two-level 4096-bin histogram top-k.
//   phase 1 (fused, only gmem scan): con -> smem + hist1 (bits 31:20) + sl1
//   scan1 -> boundary bucket B, kk
//   phase 2 (smem): acc += sum(bucket > B); hist2 on bits 19:8 of bucket B
//   scan2 -> B2, kk2
//   phase 3 (smem): acc += sum(bucket==B, bits2 > B2); + kk2 * lower_bound
// grid = N_, block = 1024, 100 KB dynamic smem. Last CTA computes mean.
// ---------------------------------------------------------------------------
__global__ __launch_bounds__(1024) void kT_tail(const float* __restrict__ ploc,
                                                const float* __restrict__ gloc,
                                                const int*   __restrict__ domain_label,
                                                const float* __restrict__ dboxes,
                                                float* __restrict__ out)
{
    extern __shared__ unsigned dyn[];
    unsigned* s_con  = dyn;            // 8736 uints
    unsigned* s_hist = dyn + 8736;     // 4 * 4096 uints

    __shared__ unsigned s_wc[32];
    __shared__ float    s_redf[32];
    __shared__ int      s_B, s_B2;
    __shared__ unsigned s_kk, s_kk2;
    __shared__ float    s_ps;
    __shared__ int      s_pn;
    __shared__ unsigned s_last;

    const int n   = blockIdx.x;
    const int tid = threadIdx.x;
    const int wid = tid >> 5, lane = tid & 31;
    const int dl  = domain_label[n];
    float rowval = 0.f;

    if (dl == 0) {
        if (tid == 0) {
            float ps = 0.f; int pp = 0;
#pragma unroll
            for (int q = 0; q < 9; q++) { ps += g_partcon[n * 16 + q]; pp += g_partpos[n * 16 + q]; }
            s_ps = ps; s_pn = pp;
        }
        for (int q = tid; q < 4 * NB; q += 1024) s_hist[q] = 0u;
        __syncthreads();
        const int pos = s_pn;

        if (pos > 0) {
            const uint4*  gc = (const uint4*)g_con + (size_t)n * A4_;
            const float4* PL = (const float4*)(ploc + (size_t)n * 4 * A_);
            const float4* GL = (const float4*)(gloc + (size_t)n * 4 * A_);
            const float4* DB = (const float4*)dboxes;
            const unsigned hb = ((unsigned)wid & 3u) * NB;

            float acc = 0.f;   // sl1 + above1 + above2 (single final reduce)

            // ===== phase 1: fused gmem scan =====
#pragma unroll
            for (int chunk = 0; chunk < 3; chunk++) {
                int grp = chunk * 1024 + tid;
                if (grp < A4_) {
                    uint4 x = __ldcg(gc + grp);
                    ((uint4*)s_con)[grp] = x;
                    atomicAdd(&s_hist[hb + (x.x >> 20)], 1u);
                    atomicAdd(&s_hist[hb + (x.y >> 20)], 1u);
                    atomicAdd(&s_hist[hb + (x.z >> 20)], 1u);
                    atomicAdd(&s_hist[hb + (x.w >> 20)], 1u);

                    bool m0 = (x.x == 0u), m1 = (x.y == 0u);
                    bool m2 = (x.z == 0u), m3 = (x.w == 0u);
                    if (m0 | m1 | m2 | m3) {
                        float4 plx = PL[0 * A4_ + grp], ply = PL[1 * A4_ + grp];
                        float4 plw = PL[2 * A4_ + grp], plh = PL[3 * A4_ + grp];
                        float4 glx = GL[0 * A4_ + grp], gly = GL[1 * A4_ + grp];
                        float4 glw = GL[2 * A4_ + grp], glh = GL[3 * A4_ + grp];
                        float4 dbx = DB[0 * A4_ + grp], dby = DB[1 * A4_ + grp];
                        float4 dbw = DB[2 * A4_ + grp], dbh = DB[3 * A4_ + grp];
#define SL1_LANE(M, PX, PY, PW, PH, GX, GY, GW, GH, DX, DY, DW, DH)           \
                        if (M) {                                              \
                            float v0 = 10.f * (GX - DX) / DW;                 \
                            float v1 = 10.f * (GY - DY) / DH;                 \
                            float v2 = 5.f * __logf(GW / DW);                 \
                            float v3 = 5.f * __logf(GH / DH);                 \
                            float d0 = PX - v0, d1 = PY - v1;                 \
                            float d2 = PW - v2, d3 = PH - v3;                 \
                            float ad;                                         \
                            ad = fabsf(d0); acc += (ad < 1.f) ? 0.5f*d0*d0 : ad-0.5f; \
                            ad = fabsf(d1); acc += (ad < 1.f) ? 0.5f*d1*d1 : ad-0.5f; \
                            ad = fabsf(d2); acc += (ad < 1.f) ? 0.5f*d2*d2 : ad-0.5f; \
                            ad = fabsf(d3); acc += (ad < 1.f) ? 0.5f*d3*d3 : ad-0.5f; \
                        }
                        SL1_LANE(m0, plx.x, ply.x, plw.x, plh.x, glx.x, gly.x, glw.x, glh.x, dbx.x, dby.x, dbw.x, dbh.x)
                        SL1_LANE(m1, plx.y, ply.y, plw.y, plh.y, glx.y, gly.y, glw.y, glh.y, dbx.y, dby.y, dbw.y, dbh.y)
                        SL1_LANE(m2, plx.z, ply.z, plw.z, plh.z, glx.z, gly.z, glw.z, glh.z, dbx.z, dby.z, dbw.z, dbh.z)
                        SL1_LANE(m3, plx.w, ply.w, plw.w, plh.w, glx.w, gly.w, glw.w, glh.w, dbx.w, dby.w, dbw.w, dbh.w)
#undef SL1_LANE
                    }
                }
            }
            __syncthreads();

            const unsigned k = (unsigned)((3 * pos > A_) ? A_ : 3 * pos);

            // ===== scan level-1: boundary bucket B, kk =====
            {
                unsigned h[4];
#pragma unroll
                for (int q = 0; q < 4; q++)
                    h[q] = s_hist[4 * tid + q] + s_hist[NB + 4 * tid + q]
                         + s_hist[2 * NB + 4 * tid + q] + s_hist[3 * NB + 4 * tid + q];
                unsigned c = h[0] + h[1] + h[2] + h[3];
#pragma unroll
                for (int o = 1; o < 32; o <<= 1) {
                    unsigned uc = __shfl_down_sync(0xffffffffu, c, o);
                    if (lane + o < 32) c += uc;
                }
                if (lane == 0) s_wc[wid] = c;
                __syncthreads();
                if (tid < 32) {
                    unsigned cc = s_wc[tid];
#pragma unroll
                    for (int o = 1; o < 32; o <<= 1) {
                        unsigned uc = __shfl_down_sync(0xffffffffu, cc, o);
                        if (tid + o < 32) cc += uc;
                    }
                    s_wc[tid] = cc;
                }
                __syncthreads();
                unsigned hi = (wid < 31) ? s_wc[wid + 1] : 0u;
                unsigned suf = c + hi;               // count of bins >= 4*tid
#pragma unroll
                for (int q = 0; q < 4; q++) {
                    unsigned gtc = suf - h[q];
                    if (k <= suf && k > gtc) { s_B = 4 * tid + q; s_kk = k - gtc; }
                    suf = gtc;
                }
            }
            __syncthreads();
            const unsigned B  = (unsigned)s_B;
            const unsigned kk = s_kk;

            // zero hist for level 2
            for (int q = tid; q < 4 * NB; q += 1024) s_hist[q] = 0u;
            __syncthreads();

            // ===== phase 2 (smem): sum above B + hist2 of bucket B =====
#pragma unroll
            for (int chunk = 0; chunk < 3; chunk++) {
                int grp = chunk * 1024 + tid;
                if (grp < A4_) {
                    uint4 x = ((const uint4*)s_con)[grp];
#define P2(V)                                                                 \
                    {                                                         \
                        unsigned b = (V) >> 20;                               \
                        if (b > B) acc += __uint_as_float(V);                 \
                        else if (b == B)                                      \
                            atomicAdd(&s_hist[hb + (((V) >> 8) & 0xFFFu)], 1u); \
                    }
                    P2(x.x) P2(x.y) P2(x.z) P2(x.w)
#undef P2
                }
            }
            __syncthreads();

            // ===== scan level-2: B2, kk2 =====
            {
                unsigned h[4];
#pragma unroll
                for (int q = 0; q < 4; q++)
                    h[q] = s_hist[4 * tid + q] + s_hist[NB + 4 * tid + q]
                         + s_hist[2 * NB + 4 * tid + q] + s_hist[3 * NB + 4 * tid + q];
                unsigned c = h[0] + h[1] + h[2] + h[3];
#pragma unroll
                for (int o = 1; o < 32; o <<= 1) {
                    unsigned uc = __shfl_down_sync(0xffffffffu, c, o);
                    if (lane + o < 32) c += uc;
                }
                if (lane == 0) s_wc[wid] = c;
                __syncthreads();
                if (tid < 32) {
                    unsigned cc = s_wc[tid];
#pragma unroll
                    for (int o = 1; o < 32; o <<= 1) {
                        unsigned uc = __shfl_down_sync(0xffffffffu, cc, o);
                        if (tid + o < 32) cc += uc;
                    }
                    s_wc[tid] = cc;
                }
                __syncthreads();
                unsigned hi = (wid < 31) ? s_wc[wid + 1] : 0u;
                unsigned suf = c + hi;
#pragma unroll
                for (int q = 0; q < 4; q++) {
                    unsigned gtc = suf - h[q];
                    if (kk <= suf && kk > gtc) { s_B2 = 4 * tid + q; s_kk2 = kk - gtc; }
                    suf = gtc;
                }
            }
            __syncthreads();
            const unsigned B2  = (unsigned)s_B2;
            const unsigned kk2 = s_kk2;

            // ===== phase 3 (smem): sum bucket-B elems with bits2 > B2 =====
#pragma unroll
            for (int chunk = 0; chunk < 3; chunk++) {
                int grp = chunk * 1024 + tid;
                if (grp < A4_) {
                    uint4 x = ((const uint4*)s_con)[grp];
#define P3(V)                                                                 \
                    if (((V) >> 20) == B && (((V) >> 8) & 0xFFFu) > B2)       \
                        acc += __uint_as_float(V);
                    P3(x.x) P3(x.y) P3(x.z) P3(x.w)
#undef P3
                }
            }

            // ===== single block reduce of acc =====
            for (int o = 16; o > 0; o >>= 1) acc += __shfl_down_sync(0xffffffffu, acc, o);
            if (lane == 0) s_redf[wid] = acc;
            __syncthreads();
            if (tid == 0) {
                float t = 0.f;
#pragma unroll
                for (int q = 0; q < 32; q++) t += s_redf[q];
                float lb = __uint_as_float((B << 20) | (B2 << 8));  // 24-bit-prefix lower bound
                rowval = (s_ps + t + (float)kk2 * lb) / (float)pos;
            }
        }
    }

    if (tid == 0) {
        g_row[n] = rowval;
        __threadfence();
        unsigned old = atomicAdd(&g_count, 1u);
        s_last = (old == N_ - 1u) ? 1u : 0u;
    }
    __syncthreads();

    if (s_last) {
        __threadfence();
        float v = (tid < N_) ? g_row[tid] : 0.f;
        for (int o = 16; o > 0; o >>= 1) v += __shfl_down_sync(0xffffffffu, v, o);
        if (lane == 0) s_redf[wid] = v;
        __syncthreads();
        if (tid == 0) {
            float t = 0.f;
#pragma unroll
            for (int q = 0; q < 4; q++) t += s_redf[q];   // warps 0-3 held 128 rows
            out[0] = t / (float)N_;
            g_count = 0u;   // reset for next graph replay
        }
    }
}

extern "C" void kernel_launch(void* const* d_in, const int* in_sizes, int n_in,
                              void* d_out, int out_size)
{
    const float* ploc         = (const float*)d_in[0];
    const float* plabel       = (const float*)d_in[1];
    const float* gloc         = (const float*)d_in[2];
    const int*   glabel       = (const int*)  d_in[3];
    const int*   domain_label = (const int*)  d_in[4];
    const float* dboxes       = (const float*)d_in[5];
    float* out = (float*)d_out;

    cudaFuncSetAttribute(kT_tail, cudaFuncAttributeMaxDynamicSharedMemorySize, DYN_BYTES);

    dim3 g1(9, N_);
    kA_focal<<<g1, 256>>>(plabel, glabel, domain_label);
    kT_tail<<<N_, 1024, DYN_BYTES>>>(ploc, gloc, domain_label, dboxes, out);
}